// round 3
// baseline (speedup 1.0000x reference)
#include <cuda_runtime.h>
#include <cuda_bf16.h>
#include <math.h>

#define B_   8
#define C_   64
#define HW   65536
#define NBC  512
#define RELP 33554432

// ---------------- scratch (__device__ globals; no allocations) ----------------
__device__ float g_sum[NBC], g_sumsq[NBC];
__device__ float g_pool[NBC * 256];   // 16x16 block SUMS per (b,c)
__device__ float g_ap[NBC * 256];     // adjoint bilinear pool per (b,c)
__device__ float g_fpm[B_ * HW];      // mean over C of f_p
__device__ float g_hp[B_];            // entropy of f_p_m_n
__device__ int   g_msbin[NBC * 256];
__device__ int   g_histms[NBC * 256];
__device__ float g_hms[NBC];
__device__ float g_na[NBC], g_meana[NBC];
__device__ int   g_pabin[B_ * 256];
__device__ int   g_histpa[B_ * 256];
__device__ float g_rowsum[B_ * 257];
__device__ float g_mi[NBC];
__device__ float g_mxv[NBC];
__device__ int   g_amx[NBC];
__device__ float g_gs[NBC];
__device__ int   g_uniq[B_];
__device__ int   g_mink[1];
__device__ int   g_order[NBC];
__device__ float g_wsel[NBC];

// ---- jax half-pixel bilinear 16->256: weights of output o on inputs j0,j1 ----
__device__ __forceinline__ void up_pair(int o, int& j0, float& w0, int& j1, float& w1) {
    int i = o >> 4, r = o & 15;
    if (r < 8) {
        float f = (float)(2 * r + 17) * (1.0f / 32.0f);
        if (i == 0) { j0 = 0; w0 = 1.0f; j1 = 0; w1 = 0.0f; }
        else        { j0 = i - 1; w0 = 1.0f - f; j1 = i; w1 = f; }
    } else {
        float f = (float)(2 * r - 15) * (1.0f / 32.0f);
        if (i == 15) { j0 = 15; w0 = 1.0f; j1 = 15; w1 = 0.0f; }
        else         { j0 = i; w0 = 1.0f - f; j1 = i + 1; w1 = f; }
    }
}
__device__ __forceinline__ float up_w(int o, int j) {
    int j0, j1; float w0, w1;
    up_pair(o, j0, w0, j1, w1);
    float r = 0.0f;
    if (j == j0) r += w0;
    if (j == j1) r += w1;
    return r;
}

// g(c) = -(c/65536)*log(c/65536 + 1e-8); safe for the (cancelling) negative args
__device__ __forceinline__ float gfun(float c) {
    float q = c * (1.0f / 65536.0f);
    return -q * logf(fmaxf(q + 1e-8f, 1e-30f));
}

__device__ __forceinline__ int bin255(float v, float mn, float mx) {
    // faithful to ((x-mn)/(mx-mn)*255).astype(int32) with IEEE div/mul
    return (int)(__fmul_rn(__fdiv_rn(v - mn, mx - mn), 255.0f));
}

// ========== K1: per-(b,c) sum, sumsq, 16x16 block sums, adjoint pool =========
__global__ void stats_kernel(const float* __restrict__ fp) {
    int bc = blockIdx.x;
    int px = threadIdx.x;           // 0..255 = column
    __shared__ float t1[16][256];   // adjoint y-reduce
    __shared__ float red[256];
    const float* base = fp + (size_t)bc * HW;
    for (int ky = 0; ky < 16; ky++) t1[ky][px] = 0.0f;
    float s = 0.0f, s2 = 0.0f, colAcc = 0.0f;
    for (int py = 0; py < 256; py++) {
        float v = base[py * 256 + px];
        s += v; s2 += v * v; colAcc += v;
        int j0, j1; float w0, w1;
        up_pair(py, j0, w0, j1, w1);
        t1[j0][px] += w0 * v;
        t1[j1][px] += w1 * v;
        if ((py & 15) == 15) {
            red[px] = colAcc;
            __syncthreads();
            if (px < 16) {
                float ps = 0.0f;
                for (int q = 0; q < 16; q++) ps += red[px * 16 + q];
                g_pool[bc * 256 + (py >> 4) * 16 + px] = ps;
            }
            __syncthreads();
            colAcc = 0.0f;
        }
    }
    red[px] = s; __syncthreads();
    for (int off = 128; off > 0; off >>= 1) { if (px < off) red[px] += red[px + off]; __syncthreads(); }
    if (px == 0) g_sum[bc] = red[0];
    __syncthreads();
    red[px] = s2; __syncthreads();
    for (int off = 128; off > 0; off >>= 1) { if (px < off) red[px] += red[px + off]; __syncthreads(); }
    if (px == 0) g_sumsq[bc] = red[0];
    __syncthreads();
    // adjoint pool: ap[ky][kx] = sum_px wx(px,kx) * t1[ky][px]
    int ky = px >> 4, kx = px & 15;
    int lo = 16 * kx - 8; if (lo < 0) lo = 0;
    int hi = 16 * kx + 24; if (hi > 256) hi = 256;
    float acc = 0.0f;
    for (int p = lo; p < hi; p++) acc += up_w(p, kx) * t1[ky][p];
    g_ap[bc * 256 + px] = acc;
}

// ========== K2: mean over C per pixel ==========
__global__ void fpm_kernel(const float* __restrict__ fp) {
    int idx = blockIdx.x * 256 + threadIdx.x;   // 0..8*65536-1
    int b = idx >> 16;
    int p = idx & 65535;
    const float* base = fp + (size_t)b * C_ * HW + p;
    float s = 0.0f;
#pragma unroll
    for (int c = 0; c < 64; c++) s += base[(size_t)c * HW];
    g_fpm[idx] = s * (1.0f / 64.0f);
}

// ========== K3: per-batch entropy of normalized f_p_m ==========
__global__ void entropyB_kernel() {
    int b = blockIdx.x, t = threadIdx.x;
    __shared__ float ra[256], rb[256];
    __shared__ int hist[256];
    const float* base = g_fpm + b * HW;
    float mn = 3.4e38f, mx = -3.4e38f;
    for (int i = t; i < HW; i += 256) { float v = base[i]; mn = fminf(mn, v); mx = fmaxf(mx, v); }
    ra[t] = mn; rb[t] = mx; __syncthreads();
    for (int off = 128; off > 0; off >>= 1) {
        if (t < off) { ra[t] = fminf(ra[t], ra[t + off]); rb[t] = fmaxf(rb[t], rb[t + off]); }
        __syncthreads();
    }
    mn = ra[0]; mx = rb[0];
    hist[t] = 0; __syncthreads();
    for (int i = t; i < HW; i += 256) atomicAdd(&hist[bin255(base[i], mn, mx)], 1);
    __syncthreads();
    float p = hist[t] * (1.0f / 65536.0f);
    ra[t] = -p * logf(p + 1e-8f);
    __syncthreads();
    for (int off = 128; off > 0; off >>= 1) { if (t < off) ra[t] += ra[t + off]; __syncthreads(); }
    if (t == 0) g_hp[b] = ra[0];
}

// ========== K4: per-(b,c) ms binning + entropy + upsample moments ==========
__global__ void ms_kernel(const float* __restrict__ fms) {
    int bc = blockIdx.x, t = threadIdx.x;   // t = pixel (also x-position)
    __shared__ float sv[256];
    __shared__ float ra[256], rb[256];
    __shared__ int hist[256];
    __shared__ int   j0t[256], j1t[256];
    __shared__ float w0t[256], w1t[256];
    float v = fms[bc * 256 + t];
    sv[t] = v;
    { int j0, j1; float w0, w1; up_pair(t, j0, w0, j1, w1); j0t[t] = j0; w0t[t] = w0; j1t[t] = j1; w1t[t] = w1; }
    ra[t] = v; rb[t] = v; __syncthreads();
    for (int off = 128; off > 0; off >>= 1) {
        if (t < off) { ra[t] = fminf(ra[t], ra[t + off]); rb[t] = fmaxf(rb[t], rb[t + off]); }
        __syncthreads();
    }
    float mn = ra[0], mx = rb[0];
    int bin = bin255(v, mn, mx);
    g_msbin[bc * 256 + t] = bin;
    hist[t] = 0; __syncthreads();
    atomicAdd(&hist[bin], 1); __syncthreads();
    g_histms[bc * 256 + t] = hist[t];
    float p = hist[t] * (1.0f / 256.0f);
    ra[t] = -p * logf(p + 1e-8f);
    __syncthreads();
    for (int off = 128; off > 0; off >>= 1) { if (t < off) ra[t] += ra[t + off]; __syncthreads(); }
    if (t == 0) g_hms[bc] = ra[0];
    __syncthreads();
    // full upsample moments: thread t = px, loop py
    int   x0 = j0t[t], x1 = j1t[t];
    float wx0 = w0t[t], wx1 = w1t[t];
    float sU = 0.0f, sU2 = 0.0f;
    for (int py = 0; py < 256; py++) {
        int   y0 = j0t[py], y1 = j1t[py];
        float wy0 = w0t[py], wy1 = w1t[py];
        float u = wy0 * (wx0 * sv[y0 * 16 + x0] + wx1 * sv[y0 * 16 + x1])
                + wy1 * (wx0 * sv[y1 * 16 + x0] + wx1 * sv[y1 * 16 + x1]);
        sU += u; sU2 += u * u;
    }
    ra[t] = sU; rb[t] = sU2; __syncthreads();
    for (int off = 128; off > 0; off >>= 1) {
        if (t < off) { ra[t] += ra[t + off]; rb[t] += rb[t + off]; }
        __syncthreads();
    }
    if (t == 0) {
        float SU = ra[0], SU2 = rb[0];
        g_meana[bc] = SU * (1.0f / 65536.0f);
        g_na[bc] = __fsqrt_rn(SU2 - SU * SU * (1.0f / 65536.0f));
    }
}

// ========== K5: f_p_a binning (mean over C of pooled) ==========
__global__ void pa_kernel() {
    int b = blockIdx.x, t = threadIdx.x;   // t = k in 16x16
    __shared__ float ra[256], rb[256];
    __shared__ int hist[256];
    float val = 0.0f;
    for (int c = 0; c < 64; c++) val += g_pool[(b * 64 + c) * 256 + t] * (1.0f / 256.0f);
    val *= (1.0f / 64.0f);
    ra[t] = val; rb[t] = val; __syncthreads();
    for (int off = 128; off > 0; off >>= 1) {
        if (t < off) { ra[t] = fminf(ra[t], ra[t + off]); rb[t] = fmaxf(rb[t], rb[t + off]); }
        __syncthreads();
    }
    float mn = ra[0], mx = rb[0];
    int bin = bin255(val, mn, mx);
    g_pabin[b * 256 + t] = bin;
    hist[t] = 0; __syncthreads();
    atomicAdd(&hist[bin], 1); __syncthreads();
    g_histpa[b * 256 + t] = hist[t];
}

// ========== K6: rowsum table per batch ==========
__global__ void rowsum_kernel() {
    int b = blockIdx.x, t = threadIdx.x;   // 288 threads, 0..256 active
    __shared__ int hp[256];
    if (t < 256) hp[t] = g_histpa[b * 256 + t];
    __syncthreads();
    if (t <= 256) {
        float acc = 0.0f;
        for (int j = 0; j < 256; j++) acc += gfun((float)(256 - t - hp[j]));
        g_rowsum[b * 257 + t] = acc;
    }
}

// ========== K7: joint entropy + mi ==========
__global__ void joint_kernel() {
    int bc = blockIdx.x, t = threadIdx.x;
    int b = bc >> 6;
    __shared__ int keys[256];
    __shared__ float red[256];
    int u = g_msbin[bc * 256 + t];
    int v = g_pabin[b * 256 + t];
    keys[t] = u * 256 + v;
    __syncthreads();
    // base: thread t handles ms-bin index t
    float acc = g_rowsum[b * 257 + g_histms[bc * 256 + t]];
    // sparse joint correction (first occurrence of each key)
    int my = keys[t], J = 0; bool first = true;
    for (int q = 0; q < 256; q++) {
        int k = keys[q];
        if (k == my) { J++; if (q < t) first = false; }
    }
    if (first) {
        float hm = (float)g_histms[bc * 256 + u];
        float hp = (float)g_histpa[b * 256 + v];
        float cold = 256.0f - hm - hp;
        acc += gfun(cold + 2.0f * (float)J) - gfun(cold);
    }
    red[t] = acc; __syncthreads();
    for (int off = 128; off > 0; off >>= 1) { if (t < off) red[t] += red[t + off]; __syncthreads(); }
    if (t == 0) g_mi[bc] = g_hp[b] + g_hms[bc] - red[0];
}

// ========== K8: softmax(mi) and rel_ms output ==========
__global__ void relms_kernel(const float* __restrict__ fms, float* __restrict__ out) {
    int b = blockIdx.x, t = threadIdx.x;
    __shared__ float mi[64];
    if (t < 64) mi[t] = g_mi[b * 64 + t];
    __syncthreads();
    if (t == 0) {
        float mx = mi[0];
        for (int c = 1; c < 64; c++) mx = fmaxf(mx, mi[c]);
        float s = 0.0f;
        for (int c = 0; c < 64; c++) { mi[c] = expf(mi[c] - mx); s += mi[c]; }
        float inv = 1.0f / s;
        for (int c = 0; c < 64; c++) mi[c] *= inv;
    }
    __syncthreads();
    for (int c = 0; c < 64; c++) {
        int i = (b * 64 + c) * 256 + t;
        float vv = fms[i];
        out[RELP + i] = vv + vv * mi[c];
    }
}

// ========== K9: similarity max/argmax over d per (b,c) ==========
__global__ void smat_kernel(const float* __restrict__ fms) {
    int bc = blockIdx.x, t = threadIdx.x;   // 64 threads, t = d
    int b = bc >> 6;
    __shared__ float ms[256];
    __shared__ float val[64];
    for (int q = t; q < 256; q += 64) ms[q] = fms[bc * 256 + q];
    __syncthreads();
    float meana = g_meana[bc];
    const float* ap = g_ap + (size_t)(b * 64 + t) * 256;
    float dot = 0.0f;
    for (int k = 0; k < 256; k++) dot += ms[k] * ap[k];
    val[t] = dot - meana * g_sum[b * 64 + t];
    __syncthreads();
    if (t == 0) {
        float mx = val[0]; int am = 0;
        for (int d = 1; d < 64; d++) if (val[d] > mx) { mx = val[d]; am = d; }
        float nb = __fsqrt_rn(g_sumsq[bc] - g_sum[bc] * g_sum[bc] * (1.0f / 65536.0f));
        float den = __fmul_rn(g_na[bc] * nb, 0.01f);   // (na*nb)/100, denominator > 0
        g_mxv[bc] = __fdiv_rn(mx, den);
        g_amx[bc] = am;
    }
}

// ========== K10: group scores per batch ==========
__global__ void groups_kernel() {
    int b = blockIdx.x, t = threadIdx.x;   // 64 threads
    __shared__ float sc[64], gsh[64];
    __shared__ int csh[64], redI[64];
    sc[t] = g_mxv[b * 64 + t]; gsh[t] = 0.0f; csh[t] = 0;
    __syncthreads();
    if (t == 0) {
        float mx = sc[0];
        for (int c = 1; c < 64; c++) mx = fmaxf(mx, sc[c]);
        float s = 0.0f;
        for (int c = 0; c < 64; c++) { sc[c] = expf(sc[c] - mx); s += sc[c]; }
        float inv = 1.0f / s;
        for (int c = 0; c < 64; c++) sc[c] *= inv;
    }
    __syncthreads();
    int idx = g_amx[b * 64 + t];
    atomicAdd(&gsh[idx], sc[t]);
    atomicAdd(&csh[idx], 1);
    __syncthreads();
    g_gs[b * 64 + t] = gsh[t];
    redI[t] = (csh[t] > 0) ? 1 : 0;
    __syncthreads();
    for (int off = 32; off > 0; off >>= 1) { if (t < off) redI[t] += redI[t + off]; __syncthreads(); }
    if (t == 0) g_uniq[b] = redI[0];
}

// ========== K11: min_k, stable descending sort, selection softmax ==========
__global__ void select_kernel() {
    int t = threadIdx.x;                 // 512 threads
    int b = t >> 6, i = t & 63;
    __shared__ int mk;
    __shared__ float sortedv[8][64];
    if (t == 0) {
        int m = g_uniq[0];
        for (int q = 1; q < 8; q++) m = min(m, g_uniq[q]);
        mk = (m + 1) >> 1;
        g_mink[0] = mk;
    }
    float vi = g_gs[b * 64 + i];
    int r = 0;
    for (int j = 0; j < 64; j++) {
        float vj = g_gs[b * 64 + j];
        if (vj > vi || (vj == vi && j < i)) r++;
    }
    g_order[b * 64 + r] = i;
    sortedv[b][r] = vi;
    __syncthreads();
    if (i == 0) {
        int m = mk;
        float mx = sortedv[b][0];   // descending: first is max
        float s = 0.0f;
        for (int q = 0; q < m; q++) { float e = expf(sortedv[b][q] - mx); sortedv[b][q] = e; s += e; }
        float inv = 1.0f / s;
        for (int q = 0; q < m; q++) g_wsel[b * 64 + q] = sortedv[b][q] * inv;
        for (int q = m; q < 64; q++) g_wsel[b * 64 + q] = 0.0f;
    }
}

// ========== K12: fused mask + rel_p output ==========
__global__ void final_kernel(const float* __restrict__ fp, float* __restrict__ out) {
    int blk = blockIdx.x;
    int b = blk >> 8;
    int p = ((blk & 255) << 8) | threadIdx.x;
    __shared__ int mk;
    __shared__ int ord[32];
    __shared__ float w[32];
    if (threadIdx.x == 0) mk = g_mink[0];
    if (threadIdx.x < 32) {
        ord[threadIdx.x] = g_order[b * 64 + threadIdx.x];
        w[threadIdx.x] = g_wsel[b * 64 + threadIdx.x];
    }
    __syncthreads();
    const float* base = fp + (size_t)b * C_ * HW;
    float mask = 0.0f;
    int m = mk;
    for (int r = 0; r < m; r++) {
        float v = base[(size_t)ord[r] * HW + p];
        mask += w[r] * (1.0f / (1.0f + expf(-v)));
    }
    float scl = 1.0f + mask;
    float* ob = out + (size_t)b * C_ * HW;
#pragma unroll
    for (int c = 0; c < 64; c++) {
        float v = base[(size_t)c * HW + p];
        ob[(size_t)c * HW + p] = v * scl;
    }
}

extern "C" void kernel_launch(void* const* d_in, const int* in_sizes, int n_in,
                              void* d_out, int out_size) {
    const float* fp  = (const float*)d_in[0];
    const float* fms = (const float*)d_in[1];
    if (n_in >= 2 && in_sizes[0] == B_ * C_ * 256) {   // defensive: swapped order
        fp  = (const float*)d_in[1];
        fms = (const float*)d_in[0];
    }
    float* out = (float*)d_out;

    stats_kernel  <<<NBC, 256>>>(fp);
    fpm_kernel    <<<(B_ * HW) / 256, 256>>>(fp);
    entropyB_kernel<<<B_, 256>>>();
    ms_kernel     <<<NBC, 256>>>(fms);
    pa_kernel     <<<B_, 256>>>();
    rowsum_kernel <<<B_, 288>>>();
    joint_kernel  <<<NBC, 256>>>();
    relms_kernel  <<<B_, 256>>>(fms, out);
    smat_kernel   <<<NBC, 64>>>(fms);
    groups_kernel <<<B_, 64>>>();
    select_kernel <<<1, 512>>>();
    final_kernel  <<<B_ * 256, 256>>>(fp, out);
}

// round 4
// speedup vs baseline: 1.5551x; 1.5551x over previous
#include <cuda_runtime.h>
#include <cuda_bf16.h>
#include <math.h>

#define B_   8
#define C_   64
#define HW   65536
#define NBC  512
#define RELP 33554432

// ---------------- scratch (__device__ globals; no allocations) ----------------
__device__ float g_sum[NBC], g_sumsq[NBC];
__device__ float g_pool[NBC * 256];   // 16x16 block SUMS per (b,c)
__device__ float g_ap[NBC * 256];     // adjoint bilinear pool per (b,c)
__device__ float g_fpm[B_ * HW];      // mean over C of f_p
__device__ float g_hp[B_];            // entropy of f_p_m_n
__device__ int   g_msbin[NBC * 256];
__device__ int   g_histms[NBC * 256];
__device__ float g_hms[NBC];
__device__ float g_na[NBC], g_meana[NBC];
__device__ int   g_pabin[B_ * 256];
__device__ int   g_histpa[B_ * 256];
__device__ float g_rowsum[B_ * 257];
__device__ float g_mi[NBC];
__device__ float g_mxv[NBC];
__device__ int   g_amx[NBC];
__device__ float g_gs[NBC];
__device__ int   g_uniq[B_];
__device__ int   g_mink[1];
__device__ int   g_order[NBC];
__device__ float g_wsel[NBC];
// stats partials + precomputed tables
__device__ float g_psum[NBC * 16], g_psumsq[NBC * 16];
__device__ float g_appart[NBC * 16 * 3 * 16];   // [bc][rg][slot][kx]
__device__ float g_G[256];                       // Gram of bilinear matrix
__device__ float g_WX[16 * 32];                  // window weights per x-bin

// ---- jax half-pixel bilinear 16->256: weights of output o on inputs j0,j1 ----
__device__ __forceinline__ void up_pair(int o, int& j0, float& w0, int& j1, float& w1) {
    int i = o >> 4, r = o & 15;
    if (r < 8) {
        float f = (float)(2 * r + 17) * (1.0f / 32.0f);
        if (i == 0) { j0 = 0; w0 = 1.0f; j1 = 0; w1 = 0.0f; }
        else        { j0 = i - 1; w0 = 1.0f - f; j1 = i; w1 = f; }
    } else {
        float f = (float)(2 * r - 15) * (1.0f / 32.0f);
        if (i == 15) { j0 = 15; w0 = 1.0f; j1 = 15; w1 = 0.0f; }
        else         { j0 = i; w0 = 1.0f - f; j1 = i + 1; w1 = f; }
    }
}
__device__ __forceinline__ float up_w(int o, int j) {
    int j0, j1; float w0, w1;
    up_pair(o, j0, w0, j1, w1);
    float r = 0.0f;
    if (j == j0) r += w0;
    if (j == j1) r += w1;
    return r;
}

__device__ __forceinline__ float gfun(float c) {
    float q = c * (1.0f / 65536.0f);
    return -q * logf(fmaxf(q + 1e-8f, 1e-30f));
}

__device__ __forceinline__ int bin255(float v, float mn, float mx) {
    return (int)(__fmul_rn(__fdiv_rn(v - mn, mx - mn), 255.0f));
}

// ========== K0: precompute Gram matrix + x-window weight table ==========
__global__ void tables_kernel() {
    int t = threadIdx.x;
    // G[i][j] = sum_o w(o,i) w(o,j)
    int i = t >> 4, j = t & 15;
    float g = 0.0f;
    for (int o = 0; o < 256; o++) g += up_w(o, i) * up_w(o, j);
    g_G[t] = g;
    // window weights: bin kx, element q -> weight of column p=16kx-8+q (0 if OOB)
    for (int e = t; e < 512; e += 256) {
        int kx = e >> 5, q = e & 31;
        int p = 16 * kx - 8 + q;
        g_WX[e] = (p >= 0 && p < 256) ? up_w(p, kx) : 0.0f;
    }
}

// ========== K1: streaming stats over f_p (one block per (b,c,rowgroup)) ======
__global__ void stats_kernel(const float* __restrict__ fp) {
    int blk = blockIdx.x;
    int bc = blk >> 4, rg = blk & 15;
    int px = threadIdx.x;
    __shared__ float sv[16 * 257];
    __shared__ float red[256];
    __shared__ float xa[16 * 17];   // [kx][o]
    __shared__ float wsh[512];
    const float* base = fp + (size_t)bc * HW + rg * 16 * 256;
    float v[16];
#pragma unroll
    for (int r = 0; r < 16; r++) v[r] = base[r * 256 + px];
    for (int e = px; e < 512; e += 256) wsh[e] = g_WX[e];
    // column sums (rows in order 0..15 — matches old per-column order)
    float cs = 0.0f, s2 = 0.0f;
#pragma unroll
    for (int r = 0; r < 16; r++) { cs += v[r]; s2 += v[r] * v[r]; }
#pragma unroll
    for (int r = 0; r < 16; r++) sv[r * 257 + px] = v[r];
    red[px] = cs;
    __syncthreads();
    // pool row (same summation order as reference kernel: cols 16kx..16kx+15)
    if (px < 16) {
        float ps = 0.0f;
        for (int q = 0; q < 16; q++) ps += red[px * 16 + q];
        g_pool[bc * 256 + rg * 16 + px] = ps;
    }
    __syncthreads();
    // sum partial
    for (int off = 128; off > 0; off >>= 1) { if (px < off) red[px] += red[px + off]; __syncthreads(); }
    if (px == 0) g_psum[bc * 16 + rg] = red[0];
    __syncthreads();
    red[px] = s2; __syncthreads();
    for (int off = 128; off > 0; off >>= 1) { if (px < off) red[px] += red[px + off]; __syncthreads(); }
    if (px == 0) g_psumsq[bc * 16 + rg] = red[0];
    // x-adjoint: thread (o = px&15, kx = px>>4): conflict-free LDS pattern
    {
        int o = px & 15, kx = px >> 4;
        int p0 = 16 * kx - 8;
        float acc = 0.0f;
#pragma unroll
        for (int q = 0; q < 32; q++) {
            int p = p0 + q;
            int pc = p < 0 ? 0 : (p > 255 ? 255 : p);
            acc += wsh[kx * 32 + q] * sv[o * 257 + pc];
        }
        xa[kx * 17 + o] = acc;
    }
    __syncthreads();
    // y-combine into 3 partial adjoint rows (ky = rg-1, rg, rg+1)
    if (px < 48) {
        int s = px >> 4, kx = px & 15;
        int ky = rg - 1 + s;
        if (ky >= 0 && ky < 16) {
            float acc = 0.0f;
            for (int o = 0; o < 16; o++)
                acc += up_w(rg * 16 + o, ky) * xa[kx * 17 + o];
            g_appart[((bc * 16 + rg) * 3 + s) * 16 + kx] = acc;
        }
    }
}

// ========== K1b: deterministic combine of stats partials ==========
__global__ void reduce_kernel() {
    int bc = blockIdx.x, t = threadIdx.x;
    if (t == 0) {
        float s = 0.0f;
        for (int r = 0; r < 16; r++) s += g_psum[bc * 16 + r];
        g_sum[bc] = s;
    } else if (t == 32) {
        float s = 0.0f;
        for (int r = 0; r < 16; r++) s += g_psumsq[bc * 16 + r];
        g_sumsq[bc] = s;
    }
    int ky = t >> 4, kx = t & 15;
    float acc = 0.0f;
    if (ky - 1 >= 0) acc += g_appart[((bc * 16 + ky - 1) * 3 + 2) * 16 + kx];
    acc += g_appart[((bc * 16 + ky) * 3 + 1) * 16 + kx];
    if (ky + 1 < 16)  acc += g_appart[((bc * 16 + ky + 1) * 3 + 0) * 16 + kx];
    g_ap[bc * 256 + t] = acc;
}

// ========== K2: mean over C per pixel (float4) ==========
__global__ void fpm_kernel(const float* __restrict__ fp) {
    int idx4 = blockIdx.x * 256 + threadIdx.x;   // 0..8*16384-1
    int b = idx4 >> 14;
    int p4 = idx4 & 16383;
    const float4* base = (const float4*)fp + (size_t)b * C_ * 16384 + p4;
    float4 s = make_float4(0.f, 0.f, 0.f, 0.f);
#pragma unroll
    for (int c = 0; c < 64; c++) {
        float4 v = base[(size_t)c * 16384];
        s.x += v.x; s.y += v.y; s.z += v.z; s.w += v.w;
    }
    const float inv = 1.0f / 64.0f;
    s.x *= inv; s.y *= inv; s.z *= inv; s.w *= inv;
    ((float4*)g_fpm)[idx4] = s;
}

// ========== K3: per-batch entropy of normalized f_p_m ==========
__global__ void entropyB_kernel() {
    int b = blockIdx.x, t = threadIdx.x;
    __shared__ float ra[256], rb[256];
    __shared__ int hist[256];
    const float* base = g_fpm + b * HW;
    float mn = 3.4e38f, mx = -3.4e38f;
    for (int i = t; i < HW; i += 256) { float v = base[i]; mn = fminf(mn, v); mx = fmaxf(mx, v); }
    ra[t] = mn; rb[t] = mx; __syncthreads();
    for (int off = 128; off > 0; off >>= 1) {
        if (t < off) { ra[t] = fminf(ra[t], ra[t + off]); rb[t] = fmaxf(rb[t], rb[t + off]); }
        __syncthreads();
    }
    mn = ra[0]; mx = rb[0];
    hist[t] = 0; __syncthreads();
    for (int i = t; i < HW; i += 256) atomicAdd(&hist[bin255(base[i], mn, mx)], 1);
    __syncthreads();
    float p = hist[t] * (1.0f / 65536.0f);
    ra[t] = -p * logf(p + 1e-8f);
    __syncthreads();
    for (int off = 128; off > 0; off >>= 1) { if (t < off) ra[t] += ra[t + off]; __syncthreads(); }
    if (t == 0) g_hp[b] = ra[0];
}

// ========== K4: per-(b,c) ms binning + entropy + Gram-form upsample moments ==
__global__ void ms_kernel(const float* __restrict__ fms) {
    int bc = blockIdx.x, t = threadIdx.x;
    __shared__ float sv[256];
    __shared__ float ra[256], rb[256];
    __shared__ int hist[256];
    __shared__ float Gsh[256], Nsh[256];
    float v = fms[bc * 256 + t];
    sv[t] = v;
    Gsh[t] = g_G[t];
    ra[t] = v; rb[t] = v; __syncthreads();
    for (int off = 128; off > 0; off >>= 1) {
        if (t < off) { ra[t] = fminf(ra[t], ra[t + off]); rb[t] = fmaxf(rb[t], rb[t + off]); }
        __syncthreads();
    }
    float mn = ra[0], mx = rb[0];
    int bin = bin255(v, mn, mx);
    g_msbin[bc * 256 + t] = bin;
    hist[t] = 0; __syncthreads();
    atomicAdd(&hist[bin], 1); __syncthreads();
    g_histms[bc * 256 + t] = hist[t];
    float p = hist[t] * (1.0f / 256.0f);
    ra[t] = -p * logf(p + 1e-8f);
    __syncthreads();
    for (int off = 128; off > 0; off >>= 1) { if (t < off) ra[t] += ra[t + off]; __syncthreads(); }
    if (t == 0) g_hms[bc] = ra[0];
    __syncthreads();
    // N = M * G   (M = sv as 16x16)
    int i = t >> 4, j = t & 15;
    float n = 0.0f;
#pragma unroll
    for (int k = 0; k < 16; k++) n += sv[i * 16 + k] * Gsh[k * 16 + j];
    Nsh[t] = n;
    __syncthreads();
    // P[i][j] = (M G M^T)[i][j]; sU2 = sum G[i][j]*P[i][j]; sU = 256*sum(M)
    float pp = 0.0f;
#pragma unroll
    for (int k = 0; k < 16; k++) pp += Nsh[i * 16 + k] * sv[j * 16 + k];
    ra[t] = Gsh[t] * pp;
    rb[t] = sv[t];
    __syncthreads();
    for (int off = 128; off > 0; off >>= 1) {
        if (t < off) { ra[t] += ra[t + off]; rb[t] += rb[t + off]; }
        __syncthreads();
    }
    if (t == 0) {
        float SU2 = ra[0];
        float SU = 256.0f * rb[0];
        g_meana[bc] = SU * (1.0f / 65536.0f);
        g_na[bc] = __fsqrt_rn(SU2 - SU * SU * (1.0f / 65536.0f));
    }
}

// ========== K5: f_p_a binning (mean over C of pooled) ==========
__global__ void pa_kernel() {
    int b = blockIdx.x, t = threadIdx.x;
    __shared__ float ra[256], rb[256];
    __shared__ int hist[256];
    float val = 0.0f;
    for (int c = 0; c < 64; c++) val += g_pool[(b * 64 + c) * 256 + t] * (1.0f / 256.0f);
    val *= (1.0f / 64.0f);
    ra[t] = val; rb[t] = val; __syncthreads();
    for (int off = 128; off > 0; off >>= 1) {
        if (t < off) { ra[t] = fminf(ra[t], ra[t + off]); rb[t] = fmaxf(rb[t], rb[t + off]); }
        __syncthreads();
    }
    float mn = ra[0], mx = rb[0];
    int bin = bin255(val, mn, mx);
    g_pabin[b * 256 + t] = bin;
    hist[t] = 0; __syncthreads();
    atomicAdd(&hist[bin], 1); __syncthreads();
    g_histpa[b * 256 + t] = hist[t];
}

// ========== K6: rowsum table per batch ==========
__global__ void rowsum_kernel() {
    int b = blockIdx.x, t = threadIdx.x;
    __shared__ int hp[256];
    if (t < 256) hp[t] = g_histpa[b * 256 + t];
    __syncthreads();
    if (t <= 256) {
        float acc = 0.0f;
        for (int j = 0; j < 256; j++) acc += gfun((float)(256 - t - hp[j]));
        g_rowsum[b * 257 + t] = acc;
    }
}

// ========== K7: joint entropy + mi ==========
__global__ void joint_kernel() {
    int bc = blockIdx.x, t = threadIdx.x;
    int b = bc >> 6;
    __shared__ int keys[256];
    __shared__ float red[256];
    int u = g_msbin[bc * 256 + t];
    int v = g_pabin[b * 256 + t];
    keys[t] = u * 256 + v;
    __syncthreads();
    float acc = g_rowsum[b * 257 + g_histms[bc * 256 + t]];
    int my = keys[t], J = 0; bool first = true;
    for (int q = 0; q < 256; q++) {
        int k = keys[q];
        if (k == my) { J++; if (q < t) first = false; }
    }
    if (first) {
        float hm = (float)g_histms[bc * 256 + u];
        float hp = (float)g_histpa[b * 256 + v];
        float cold = 256.0f - hm - hp;
        acc += gfun(cold + 2.0f * (float)J) - gfun(cold);
    }
    red[t] = acc; __syncthreads();
    for (int off = 128; off > 0; off >>= 1) { if (t < off) red[t] += red[t + off]; __syncthreads(); }
    if (t == 0) g_mi[bc] = g_hp[b] + g_hms[bc] - red[0];
}

// ========== K8: softmax(mi) and rel_ms output ==========
__global__ void relms_kernel(const float* __restrict__ fms, float* __restrict__ out) {
    int b = blockIdx.x, t = threadIdx.x;
    __shared__ float mi[64];
    if (t < 64) mi[t] = g_mi[b * 64 + t];
    __syncthreads();
    if (t == 0) {
        float mx = mi[0];
        for (int c = 1; c < 64; c++) mx = fmaxf(mx, mi[c]);
        float s = 0.0f;
        for (int c = 0; c < 64; c++) { mi[c] = expf(mi[c] - mx); s += mi[c]; }
        float inv = 1.0f / s;
        for (int c = 0; c < 64; c++) mi[c] *= inv;
    }
    __syncthreads();
    for (int c = 0; c < 64; c++) {
        int i = (b * 64 + c) * 256 + t;
        float vv = fms[i];
        out[RELP + i] = vv + vv * mi[c];
    }
}

// ========== K9: similarity max/argmax over d per (b,c) ==========
__global__ void smat_kernel(const float* __restrict__ fms) {
    int bc = blockIdx.x, t = threadIdx.x;   // 64 threads, t = d
    int b = bc >> 6;
    __shared__ float ms[256];
    __shared__ float val[64];
    for (int q = t; q < 256; q += 64) ms[q] = fms[bc * 256 + q];
    __syncthreads();
    float meana = g_meana[bc];
    const float* ap = g_ap + (size_t)(b * 64 + t) * 256;
    float dot = 0.0f;
    for (int k = 0; k < 256; k++) dot += ms[k] * ap[k];
    val[t] = dot - meana * g_sum[b * 64 + t];
    __syncthreads();
    if (t == 0) {
        float mx = val[0]; int am = 0;
        for (int d = 1; d < 64; d++) if (val[d] > mx) { mx = val[d]; am = d; }
        float nb = __fsqrt_rn(g_sumsq[bc] - g_sum[bc] * g_sum[bc] * (1.0f / 65536.0f));
        float den = __fmul_rn(g_na[bc] * nb, 0.01f);
        g_mxv[bc] = __fdiv_rn(mx, den);
        g_amx[bc] = am;
    }
}

// ========== K10: group scores per batch ==========
__global__ void groups_kernel() {
    int b = blockIdx.x, t = threadIdx.x;
    __shared__ float sc[64], gsh[64];
    __shared__ int csh[64], redI[64];
    sc[t] = g_mxv[b * 64 + t]; gsh[t] = 0.0f; csh[t] = 0;
    __syncthreads();
    if (t == 0) {
        float mx = sc[0];
        for (int c = 1; c < 64; c++) mx = fmaxf(mx, sc[c]);
        float s = 0.0f;
        for (int c = 0; c < 64; c++) { sc[c] = expf(sc[c] - mx); s += sc[c]; }
        float inv = 1.0f / s;
        for (int c = 0; c < 64; c++) sc[c] *= inv;
    }
    __syncthreads();
    int idx = g_amx[b * 64 + t];
    atomicAdd(&gsh[idx], sc[t]);
    atomicAdd(&csh[idx], 1);
    __syncthreads();
    g_gs[b * 64 + t] = gsh[t];
    redI[t] = (csh[t] > 0) ? 1 : 0;
    __syncthreads();
    for (int off = 32; off > 0; off >>= 1) { if (t < off) redI[t] += redI[t + off]; __syncthreads(); }
    if (t == 0) g_uniq[b] = redI[0];
}

// ========== K11: min_k, stable descending sort, selection softmax ==========
__global__ void select_kernel() {
    int t = threadIdx.x;
    int b = t >> 6, i = t & 63;
    __shared__ int mk;
    __shared__ float sortedv[8][64];
    if (t == 0) {
        int m = g_uniq[0];
        for (int q = 1; q < 8; q++) m = min(m, g_uniq[q]);
        mk = (m + 1) >> 1;
        g_mink[0] = mk;
    }
    float vi = g_gs[b * 64 + i];
    int r = 0;
    for (int j = 0; j < 64; j++) {
        float vj = g_gs[b * 64 + j];
        if (vj > vi || (vj == vi && j < i)) r++;
    }
    g_order[b * 64 + r] = i;
    sortedv[b][r] = vi;
    __syncthreads();
    if (i == 0) {
        int m = mk;
        float mx = sortedv[b][0];
        float s = 0.0f;
        for (int q = 0; q < m; q++) { float e = expf(sortedv[b][q] - mx); sortedv[b][q] = e; s += e; }
        float inv = 1.0f / s;
        for (int q = 0; q < m; q++) g_wsel[b * 64 + q] = sortedv[b][q] * inv;
        for (int q = m; q < 64; q++) g_wsel[b * 64 + q] = 0.0f;
    }
}

// ========== K12: fused mask + rel_p output (float4) ==========
__global__ void final_kernel(const float* __restrict__ fp, float* __restrict__ out) {
    int blk = blockIdx.x;               // 512 blocks
    int b = blk >> 6;
    int p4 = ((blk & 63) << 8) | threadIdx.x;   // float4 index 0..16383
    __shared__ int mk;
    __shared__ int ord[32];
    __shared__ float w[32];
    if (threadIdx.x == 0) mk = g_mink[0];
    if (threadIdx.x < 32) {
        ord[threadIdx.x] = g_order[b * 64 + threadIdx.x];
        w[threadIdx.x] = g_wsel[b * 64 + threadIdx.x];
    }
    __syncthreads();
    const float4* base = (const float4*)fp + (size_t)b * C_ * 16384;
    float4 m = make_float4(0.f, 0.f, 0.f, 0.f);
    int mkk = mk;
    for (int r = 0; r < mkk; r++) {
        float4 v = base[(size_t)ord[r] * 16384 + p4];
        float ww = w[r];
        m.x += ww / (1.0f + expf(-v.x));
        m.y += ww / (1.0f + expf(-v.y));
        m.z += ww / (1.0f + expf(-v.z));
        m.w += ww / (1.0f + expf(-v.w));
    }
    float4 scl = make_float4(1.0f + m.x, 1.0f + m.y, 1.0f + m.z, 1.0f + m.w);
    float4* ob = (float4*)out + (size_t)b * C_ * 16384;
#pragma unroll 8
    for (int c = 0; c < 64; c++) {
        float4 v = base[(size_t)c * 16384 + p4];
        v.x *= scl.x; v.y *= scl.y; v.z *= scl.z; v.w *= scl.w;
        ob[(size_t)c * 16384 + p4] = v;
    }
}

extern "C" void kernel_launch(void* const* d_in, const int* in_sizes, int n_in,
                              void* d_out, int out_size) {
    const float* fp  = (const float*)d_in[0];
    const float* fms = (const float*)d_in[1];
    if (n_in >= 2 && in_sizes[0] == B_ * C_ * 256) {
        fp  = (const float*)d_in[1];
        fms = (const float*)d_in[0];
    }
    float* out = (float*)d_out;

    tables_kernel <<<1, 256>>>();
    stats_kernel  <<<NBC * 16, 256>>>(fp);
    fpm_kernel    <<<512, 256>>>(fp);
    reduce_kernel <<<NBC, 256>>>();
    entropyB_kernel<<<B_, 256>>>();
    ms_kernel     <<<NBC, 256>>>(fms);
    pa_kernel     <<<B_, 256>>>();
    rowsum_kernel <<<B_, 288>>>();
    joint_kernel  <<<NBC, 256>>>();
    relms_kernel  <<<B_, 256>>>(fms, out);
    smat_kernel   <<<NBC, 64>>>(fms);
    groups_kernel <<<B_, 64>>>();
    select_kernel <<<1, 512>>>();
    final_kernel  <<<512, 256>>>(fp, out);
}

// round 5
// speedup vs baseline: 1.7609x; 1.1324x over previous
#include <cuda_runtime.h>
#include <cuda_bf16.h>
#include <math.h>

#define B_   8
#define C_   64
#define HW   65536
#define NBC  512
#define RELP 33554432

// ---------------- scratch (__device__ globals; no allocations) ----------------
__device__ float g_sum[NBC], g_sumsq[NBC];
__device__ float g_pool[NBC * 256];
__device__ float g_ap[NBC * 256];
__device__ float g_fpm[B_ * HW];
__device__ float g_hp[B_];
__device__ int   g_msbin[NBC * 256];
__device__ int   g_histms[NBC * 256];
__device__ float g_hms[NBC];
__device__ float g_na[NBC], g_meana[NBC];
__device__ int   g_pabin[B_ * 256];
__device__ int   g_histpa[B_ * 256];
__device__ float g_rowsum[B_ * 257];
__device__ float g_mi[NBC];
__device__ float g_mxv[NBC];
__device__ int   g_amx[NBC];
__device__ float g_gs[NBC];
__device__ int   g_mink[1];
__device__ int   g_order[NBC];
__device__ float g_wsel[NBC];
__device__ float g_psum[NBC * 16], g_psumsq[NBC * 16];
__device__ float g_appart[NBC * 16 * 3 * 16];
__device__ float g_G[256];
__device__ float g_WX[16 * 32];
__device__ float g_gt[513];                  // g(idx-256) table
__device__ float g_fmn[512], g_fmx[512];     // fpm per-block min/max partials

// ---- jax half-pixel bilinear 16->256 weights ----
__device__ __forceinline__ void up_pair(int o, int& j0, float& w0, int& j1, float& w1) {
    int i = o >> 4, r = o & 15;
    if (r < 8) {
        float f = (float)(2 * r + 17) * (1.0f / 32.0f);
        if (i == 0) { j0 = 0; w0 = 1.0f; j1 = 0; w1 = 0.0f; }
        else        { j0 = i - 1; w0 = 1.0f - f; j1 = i; w1 = f; }
    } else {
        float f = (float)(2 * r - 15) * (1.0f / 32.0f);
        if (i == 15) { j0 = 15; w0 = 1.0f; j1 = 15; w1 = 0.0f; }
        else         { j0 = i; w0 = 1.0f - f; j1 = i + 1; w1 = f; }
    }
}
__device__ __forceinline__ float up_w(int o, int j) {
    int j0, j1; float w0, w1;
    up_pair(o, j0, w0, j1, w1);
    float r = 0.0f;
    if (j == j0) r += w0;
    if (j == j1) r += w1;
    return r;
}

__device__ __forceinline__ float gfun(float c) {
    float q = c * (1.0f / 65536.0f);
    return -q * logf(fmaxf(q + 1e-8f, 1e-30f));
}
__device__ __forceinline__ int bin255(float v, float mn, float mx) {
    return (int)(__fmul_rn(__fdiv_rn(v - mn, mx - mn), 255.0f));
}

// ========== K0: tables ==========
__global__ void tables_kernel() {
    int t = threadIdx.x;
    int i = t >> 4, j = t & 15;
    float g = 0.0f;
    for (int o = 0; o < 256; o++) g += up_w(o, i) * up_w(o, j);
    g_G[t] = g;
    for (int e = t; e < 512; e += 256) {
        int kx = e >> 5, q = e & 31;
        int p = 16 * kx - 8 + q;
        g_WX[e] = (p >= 0 && p < 256) ? up_w(p, kx) : 0.0f;
    }
    for (int e = t; e < 513; e += 256) g_gt[e] = gfun((float)(e - 256));
}

// ========== K1: fused streaming pass: stats blocks + fpm blocks ==========
__global__ void bigpass_kernel(const float* __restrict__ fp) {
    __shared__ float sv[16 * 257];
    __shared__ float red[256];
    __shared__ float xa[16 * 17];
    __shared__ float wsh[512];
    int blk = blockIdx.x;
    int px = threadIdx.x;
    if (blk < 8192) {
        // ---- stats over one (bc, rowgroup) ----
        int bc = blk >> 4, rg = blk & 15;
        const float* base = fp + (size_t)bc * HW + rg * 16 * 256;
        float v[16];
#pragma unroll
        for (int r = 0; r < 16; r++) v[r] = base[r * 256 + px];
        for (int e = px; e < 512; e += 256) wsh[e] = g_WX[e];
        float cs = 0.0f, s2 = 0.0f;
#pragma unroll
        for (int r = 0; r < 16; r++) { cs += v[r]; s2 += v[r] * v[r]; }
#pragma unroll
        for (int r = 0; r < 16; r++) sv[r * 257 + px] = v[r];
        red[px] = cs;
        __syncthreads();
        if (px < 16) {
            float ps = 0.0f;
            for (int q = 0; q < 16; q++) ps += red[px * 16 + q];
            g_pool[bc * 256 + rg * 16 + px] = ps;
        }
        __syncthreads();
        for (int off = 128; off > 0; off >>= 1) { if (px < off) red[px] += red[px + off]; __syncthreads(); }
        if (px == 0) g_psum[bc * 16 + rg] = red[0];
        __syncthreads();
        red[px] = s2; __syncthreads();
        for (int off = 128; off > 0; off >>= 1) { if (px < off) red[px] += red[px + off]; __syncthreads(); }
        if (px == 0) g_psumsq[bc * 16 + rg] = red[0];
        {
            int o = px & 15, kx = px >> 4;
            int p0 = 16 * kx - 8;
            float acc = 0.0f;
#pragma unroll
            for (int q = 0; q < 32; q++) {
                int p = p0 + q;
                int pc = p < 0 ? 0 : (p > 255 ? 255 : p);
                acc += wsh[kx * 32 + q] * sv[o * 257 + pc];
            }
            xa[kx * 17 + o] = acc;
        }
        __syncthreads();
        if (px < 48) {
            int s = px >> 4, kx = px & 15;
            int ky = rg - 1 + s;
            if (ky >= 0 && ky < 16) {
                float acc = 0.0f;
                for (int o = 0; o < 16; o++)
                    acc += up_w(rg * 16 + o, ky) * xa[kx * 17 + o];
                g_appart[((bc * 16 + rg) * 3 + s) * 16 + kx] = acc;
            }
        }
    } else {
        // ---- fpm: mean over C (float4) + per-block min/max partials ----
        int fblk = blk - 8192;                 // 0..511
        int idx4 = fblk * 256 + px;
        int b = idx4 >> 14;
        int p4 = idx4 & 16383;
        const float4* base = (const float4*)fp + (size_t)b * C_ * 16384 + p4;
        float4 s = make_float4(0.f, 0.f, 0.f, 0.f);
#pragma unroll 16
        for (int c = 0; c < 64; c++) {
            float4 v = base[(size_t)c * 16384];
            s.x += v.x; s.y += v.y; s.z += v.z; s.w += v.w;
        }
        const float inv = 1.0f / 64.0f;
        s.x *= inv; s.y *= inv; s.z *= inv; s.w *= inv;
        ((float4*)g_fpm)[idx4] = s;
        float mn = fminf(fminf(s.x, s.y), fminf(s.z, s.w));
        float mx = fmaxf(fmaxf(s.x, s.y), fmaxf(s.z, s.w));
        red[px] = mn;
        sv[px] = mx;
        __syncthreads();
        for (int off = 128; off > 0; off >>= 1) {
            if (px < off) {
                red[px] = fminf(red[px], red[px + off]);
                sv[px] = fmaxf(sv[px], sv[px + off]);
            }
            __syncthreads();
        }
        if (px == 0) { g_fmn[fblk] = red[0]; g_fmx[fblk] = sv[0]; }
    }
}

// ========== K2: combine stats partials ==========
__global__ void reduce_kernel() {
    int bc = blockIdx.x, t = threadIdx.x;
    if (t == 0) {
        float s = 0.0f;
        for (int r = 0; r < 16; r++) s += g_psum[bc * 16 + r];
        g_sum[bc] = s;
    } else if (t == 32) {
        float s = 0.0f;
        for (int r = 0; r < 16; r++) s += g_psumsq[bc * 16 + r];
        g_sumsq[bc] = s;
    }
    int ky = t >> 4;
    float acc = 0.0f;
    if (ky - 1 >= 0) acc += g_appart[((bc * 16 + ky - 1) * 3 + 2) * 16 + (t & 15)];
    acc += g_appart[((bc * 16 + ky) * 3 + 1) * 16 + (t & 15)];
    if (ky + 1 < 16)  acc += g_appart[((bc * 16 + ky + 1) * 3 + 0) * 16 + (t & 15)];
    g_ap[bc * 256 + t] = acc;
}

// ========== K3: per-batch entropy of normalized f_p_m (minmax from partials) ==
__global__ void entropyB_kernel() {
    int b = blockIdx.x, t = threadIdx.x;
    __shared__ float ra[256], rb[256];
    __shared__ int hist[256];
    if (t < 64) { ra[t] = g_fmn[b * 64 + t]; rb[t] = g_fmx[b * 64 + t]; }
    else        { ra[t] = 3.4e38f; rb[t] = -3.4e38f; }
    __syncthreads();
    for (int off = 128; off > 0; off >>= 1) {
        if (t < off) { ra[t] = fminf(ra[t], ra[t + off]); rb[t] = fmaxf(rb[t], rb[t + off]); }
        __syncthreads();
    }
    float mn = ra[0], mx = rb[0];
    hist[t] = 0; __syncthreads();
    const float* base = g_fpm + b * HW;
    for (int i = t; i < HW; i += 256) atomicAdd(&hist[bin255(base[i], mn, mx)], 1);
    __syncthreads();
    float p = hist[t] * (1.0f / 65536.0f);
    ra[t] = -p * logf(p + 1e-8f);
    __syncthreads();
    for (int off = 128; off > 0; off >>= 1) { if (t < off) ra[t] += ra[t + off]; __syncthreads(); }
    if (t == 0) g_hp[b] = ra[0];
}

// ========== K4: ms binning + entropy + Gram moments ==========
__global__ void ms_kernel(const float* __restrict__ fms) {
    int bc = blockIdx.x, t = threadIdx.x;
    __shared__ float sv[256];
    __shared__ float ra[256], rb[256];
    __shared__ int hist[256];
    __shared__ float Gsh[256], Nsh[256];
    float v = fms[bc * 256 + t];
    sv[t] = v;
    Gsh[t] = g_G[t];
    ra[t] = v; rb[t] = v; __syncthreads();
    for (int off = 128; off > 0; off >>= 1) {
        if (t < off) { ra[t] = fminf(ra[t], ra[t + off]); rb[t] = fmaxf(rb[t], rb[t + off]); }
        __syncthreads();
    }
    float mn = ra[0], mx = rb[0];
    int bin = bin255(v, mn, mx);
    g_msbin[bc * 256 + t] = bin;
    hist[t] = 0; __syncthreads();
    atomicAdd(&hist[bin], 1); __syncthreads();
    g_histms[bc * 256 + t] = hist[t];
    float p = hist[t] * (1.0f / 256.0f);
    ra[t] = -p * logf(p + 1e-8f);
    __syncthreads();
    for (int off = 128; off > 0; off >>= 1) { if (t < off) ra[t] += ra[t + off]; __syncthreads(); }
    if (t == 0) g_hms[bc] = ra[0];
    __syncthreads();
    int i = t >> 4, j = t & 15;
    float n = 0.0f;
#pragma unroll
    for (int k = 0; k < 16; k++) n += sv[i * 16 + k] * Gsh[k * 16 + j];
    Nsh[t] = n;
    __syncthreads();
    float pp = 0.0f;
#pragma unroll
    for (int k = 0; k < 16; k++) pp += Nsh[i * 16 + k] * sv[j * 16 + k];
    ra[t] = Gsh[t] * pp;
    rb[t] = sv[t];
    __syncthreads();
    for (int off = 128; off > 0; off >>= 1) {
        if (t < off) { ra[t] += ra[t + off]; rb[t] += rb[t + off]; }
        __syncthreads();
    }
    if (t == 0) {
        float SU2 = ra[0];
        float SU = 256.0f * rb[0];
        g_meana[bc] = SU * (1.0f / 65536.0f);
        g_na[bc] = __fsqrt_rn(SU2 - SU * SU * (1.0f / 65536.0f));
    }
}

// ========== K5: f_p_a binning + rowsum table (merged) ==========
__global__ void parow_kernel() {
    int b = blockIdx.x, t = threadIdx.x;
    __shared__ float ra[256], rb[256];
    __shared__ int hist[256];
    __shared__ float gts[513];
    float val = 0.0f;
    for (int c = 0; c < 64; c++) val += g_pool[(b * 64 + c) * 256 + t] * (1.0f / 256.0f);
    val *= (1.0f / 64.0f);
    for (int e = t; e < 513; e += 256) gts[e] = g_gt[e];
    ra[t] = val; rb[t] = val; __syncthreads();
    for (int off = 128; off > 0; off >>= 1) {
        if (t < off) { ra[t] = fminf(ra[t], ra[t + off]); rb[t] = fmaxf(rb[t], rb[t + off]); }
        __syncthreads();
    }
    float mn = ra[0], mx = rb[0];
    int bin = bin255(val, mn, mx);
    g_pabin[b * 256 + t] = bin;
    hist[t] = 0; __syncthreads();
    atomicAdd(&hist[bin], 1); __syncthreads();
    g_histpa[b * 256 + t] = hist[t];
    __syncthreads();
    // rowsum[u] = sum_j g(256 - u - hp[j]) = sum_j gts[512 - u - hist[j]]
    float acc = 0.0f;
    for (int j = 0; j < 256; j++) acc += gts[512 - t - hist[j]];
    g_rowsum[b * 257 + t] = acc;
    if (t == 0) {
        float a2 = 0.0f;
        for (int j = 0; j < 256; j++) a2 += gts[256 - hist[j]];
        g_rowsum[b * 257 + 256] = a2;
    }
}

// ========== K6: joint entropy + mi ==========
__global__ void joint_kernel() {
    int bc = blockIdx.x, t = threadIdx.x;
    int b = bc >> 6;
    __shared__ int keys[256];
    __shared__ float red[256];
    __shared__ float gts[513];
    int u = g_msbin[bc * 256 + t];
    int v = g_pabin[b * 256 + t];
    keys[t] = u * 256 + v;
    for (int e = t; e < 513; e += 256) gts[e] = g_gt[e];
    __syncthreads();
    float acc = g_rowsum[b * 257 + g_histms[bc * 256 + t]];
    int my = keys[t], J = 0; bool first = true;
    for (int q = 0; q < 256; q++) {
        int k = keys[q];
        if (k == my) { J++; if (q < t) first = false; }
    }
    if (first) {
        int hm = g_histms[bc * 256 + u];
        int hp = g_histpa[b * 256 + v];
        int cold = 256 - hm - hp;
        acc += gts[cold + 2 * J + 256] - gts[cold + 256];
    }
    red[t] = acc; __syncthreads();
    for (int off = 128; off > 0; off >>= 1) { if (t < off) red[t] += red[t + off]; __syncthreads(); }
    if (t == 0) g_mi[bc] = g_hp[b] + g_hms[bc] - red[0];
}

// ========== K7: softmax(mi) and rel_ms output ==========
__global__ void relms_kernel(const float* __restrict__ fms, float* __restrict__ out) {
    int b = blockIdx.x, t = threadIdx.x;
    __shared__ float mi[64];
    if (t < 64) mi[t] = g_mi[b * 64 + t];
    __syncthreads();
    if (t == 0) {
        float mx = mi[0];
        for (int c = 1; c < 64; c++) mx = fmaxf(mx, mi[c]);
        float s = 0.0f;
        for (int c = 0; c < 64; c++) { mi[c] = expf(mi[c] - mx); s += mi[c]; }
        float inv = 1.0f / s;
        for (int c = 0; c < 64; c++) mi[c] *= inv;
    }
    __syncthreads();
    for (int c = 0; c < 64; c++) {
        int i = (b * 64 + c) * 256 + t;
        float vv = fms[i];
        out[RELP + i] = vv + vv * mi[c];
    }
}

// ========== K8: similarity max/argmax (coalesced shared tiles, 2 halves) =====
__global__ void smat_kernel(const float* __restrict__ fms) {
    int bc = blockIdx.x, t = threadIdx.x;   // 256 threads
    int b = bc >> 6;
    __shared__ float ms[256];
    __shared__ float sap[32 * 257];
    __shared__ float val[64];
    ms[t] = fms[bc * 256 + t];
    float meana = g_meana[bc];
    for (int h = 0; h < 2; h++) {
        __syncthreads();
        for (int i = 0; i < 32; i++)
            sap[i * 257 + t] = g_ap[(size_t)(b * 64 + h * 32 + i) * 256 + t];
        __syncthreads();
        if ((t >> 5) == h && t < 64) {
            int row = t & 31;
            float dot = 0.0f;
#pragma unroll 8
            for (int k = 0; k < 256; k++) dot += ms[k] * sap[row * 257 + k];
            val[t] = dot - meana * g_sum[b * 64 + t];
        }
    }
    __syncthreads();
    if (t == 0) {
        float mx = val[0]; int am = 0;
        for (int d = 1; d < 64; d++) if (val[d] > mx) { mx = val[d]; am = d; }
        float nb = __fsqrt_rn(g_sumsq[bc] - g_sum[bc] * g_sum[bc] * (1.0f / 65536.0f));
        float den = __fmul_rn(g_na[bc] * nb, 0.01f);
        g_mxv[bc] = __fdiv_rn(mx, den);
        g_amx[bc] = am;
    }
}

// ========== K9: groups + min_k + sort + selection softmax (merged) ==========
__global__ void grpsel_kernel() {
    int t = threadIdx.x;                 // 512 threads
    int b = t >> 6, i = t & 63;
    __shared__ float sc[8][64], gsh[8][64], sortedv[8][64];
    __shared__ int csh[8][64];
    __shared__ int uniq[8];
    __shared__ int mk;
    sc[b][i] = g_mxv[b * 64 + i];
    gsh[b][i] = 0.0f; csh[b][i] = 0;
    __syncthreads();
    if (i == 0) {
        float mx = sc[b][0];
        for (int c = 1; c < 64; c++) mx = fmaxf(mx, sc[b][c]);
        float s = 0.0f;
        for (int c = 0; c < 64; c++) { sc[b][c] = expf(sc[b][c] - mx); s += sc[b][c]; }
        float inv = 1.0f / s;
        for (int c = 0; c < 64; c++) sc[b][c] *= inv;
    }
    __syncthreads();
    int idx = g_amx[b * 64 + i];
    atomicAdd(&gsh[b][idx], sc[b][i]);
    atomicAdd(&csh[b][idx], 1);
    __syncthreads();
    if (i == 0) {
        int u = 0;
        for (int j = 0; j < 64; j++) u += (csh[b][j] > 0) ? 1 : 0;
        uniq[b] = u;
    }
    __syncthreads();
    if (t == 0) {
        int m = uniq[0];
        for (int q = 1; q < 8; q++) m = min(m, uniq[q]);
        mk = (m + 1) >> 1;
        g_mink[0] = mk;
    }
    float vi = gsh[b][i];
    int r = 0;
    for (int j = 0; j < 64; j++) {
        float vj = gsh[b][j];
        if (vj > vi || (vj == vi && j < i)) r++;
    }
    g_order[b * 64 + r] = i;
    sortedv[b][r] = vi;
    __syncthreads();
    if (i == 0) {
        int m = mk;
        float mx = sortedv[b][0];
        float s = 0.0f;
        for (int q = 0; q < m; q++) { float e = expf(sortedv[b][q] - mx); sortedv[b][q] = e; s += e; }
        float inv = 1.0f / s;
        for (int q = 0; q < m; q++) g_wsel[b * 64 + q] = sortedv[b][q] * inv;
        for (int q = m; q < 64; q++) g_wsel[b * 64 + q] = 0.0f;
    }
}

// ========== K10: fused mask + rel_p output (float4) ==========
__global__ void final_kernel(const float* __restrict__ fp, float* __restrict__ out) {
    int blk = blockIdx.x;
    int b = blk >> 6;
    int p4 = ((blk & 63) << 8) | threadIdx.x;
    __shared__ int mk;
    __shared__ int ord[32];
    __shared__ float w[32];
    if (threadIdx.x == 0) mk = g_mink[0];
    if (threadIdx.x < 32) {
        ord[threadIdx.x] = g_order[b * 64 + threadIdx.x];
        w[threadIdx.x] = g_wsel[b * 64 + threadIdx.x];
    }
    __syncthreads();
    const float4* base = (const float4*)fp + (size_t)b * C_ * 16384;
    float4 m = make_float4(0.f, 0.f, 0.f, 0.f);
    int mkk = mk;
    for (int r = 0; r < mkk; r++) {
        float4 v = base[(size_t)ord[r] * 16384 + p4];
        float ww = w[r];
        m.x += ww / (1.0f + expf(-v.x));
        m.y += ww / (1.0f + expf(-v.y));
        m.z += ww / (1.0f + expf(-v.z));
        m.w += ww / (1.0f + expf(-v.w));
    }
    float4 scl = make_float4(1.0f + m.x, 1.0f + m.y, 1.0f + m.z, 1.0f + m.w);
    float4* ob = (float4*)out + (size_t)b * C_ * 16384;
#pragma unroll 8
    for (int c = 0; c < 64; c++) {
        float4 v = base[(size_t)c * 16384 + p4];
        v.x *= scl.x; v.y *= scl.y; v.z *= scl.z; v.w *= scl.w;
        ob[(size_t)c * 16384 + p4] = v;
    }
}

extern "C" void kernel_launch(void* const* d_in, const int* in_sizes, int n_in,
                              void* d_out, int out_size) {
    const float* fp  = (const float*)d_in[0];
    const float* fms = (const float*)d_in[1];
    if (n_in >= 2 && in_sizes[0] == B_ * C_ * 256) {
        fp  = (const float*)d_in[1];
        fms = (const float*)d_in[0];
    }
    float* out = (float*)d_out;

    tables_kernel  <<<1, 256>>>();
    bigpass_kernel <<<8192 + 512, 256>>>(fp);
    reduce_kernel  <<<NBC, 256>>>();
    entropyB_kernel<<<B_, 256>>>();
    ms_kernel      <<<NBC, 256>>>(fms);
    parow_kernel   <<<B_, 256>>>();
    joint_kernel   <<<NBC, 256>>>();
    relms_kernel   <<<B_, 256>>>(fms, out);
    smat_kernel    <<<NBC, 256>>>(fms);
    grpsel_kernel  <<<1, 512>>>();
    final_kernel   <<<NBC, 256>>>(fp, out);
}